// round 11
// baseline (speedup 1.0000x reference)
#include <cuda_runtime.h>

// HexEye: mean over 9x9 reflect-padded patches at 721 receptor centers,
// for 32 batches x 3 channels of a 600x800 fp32 image.
//
// d_in[0]: stim float32 [32,3,600,800]   d_in[1]: rx int32[721]
// d_in[2]: ry int32[721]                 d_out  : float32 [32,3,721]
//
// One warp per (plane-group of 4, receptor PAIR), software-pipelined:
//   loads(A) -> consume(A) -> loads(B) -> reduce+store(A) [under B's load
//   latency] -> consume+reduce+store(B).
// Fast path: lane -> (row=lane/3, seg=lane%3); one aligned float4 per lane,
// so one LDG.128 with 27 lanes fetches a full 9x9 patch per plane.
// Border receptors use an exact jnp-'reflect' scalar fallback.

#define HEX_H     600
#define HEX_W     800
#define HEX_K     9
#define HEX_PAD   4
#define HEX_NOMM  721
#define HEX_BC    96
#define HEX_G     4                          // planes per warp
#define HEX_NGRP  (HEX_BC / HEX_G)           // 24
#define HEX_NPAIR ((HEX_NOMM + 1) / 2)       // 361
#define HEX_NWARP (HEX_NGRP * HEX_NPAIR)     // 8664
#define PLANE     (HEX_H * HEX_W)

__device__ __forceinline__ void make_patch(const int* __restrict__ rx,
                                           const int* __restrict__ ry,
                                           int o, int e0,
                                           int& m0, int& n0, int& base,
                                           float& wx, float& wy, float& wz, float& ww,
                                           bool& interior)
{
    int cx = __ldg(&rx[o]);
    int cy = __ldg(&ry[o]);
    cx = min(max(cx, HEX_PAD), HEX_W + HEX_PAD - 1);
    cy = min(max(cy, HEX_PAD), HEX_H + HEX_PAD - 1);
    m0   = cy - 2 * HEX_PAD;
    n0   = cx - 2 * HEX_PAD;
    base = n0 & ~3;
    const int w0 = n0 & 3;
    wx = ((e0 + 0 >= w0) & (e0 + 0 < w0 + HEX_K)) ? 1.0f : 0.0f;
    wy = ((e0 + 1 >= w0) & (e0 + 1 < w0 + HEX_K)) ? 1.0f : 0.0f;
    wz = ((e0 + 2 >= w0) & (e0 + 2 < w0 + HEX_K)) ? 1.0f : 0.0f;
    ww = ((e0 + 3 >= w0) & (e0 + 3 < w0 + HEX_K)) ? 1.0f : 0.0f;
    interior = (m0 >= 0) & (m0 + HEX_K <= HEX_H) &
               (base >= 0) & (base + 12 <= HEX_W);
}

// exact jnp-'reflect' scalar gather (border receptors; rare)
__device__ __noinline__ void gather_scalar(const float* __restrict__ img0,
                                           int m0, int n0, int lane, float s[HEX_G])
{
    #pragma unroll
    for (int i = 0; i < 3; i++) {
        const int idx = lane + 32 * i;
        if (idx < HEX_K * HEX_K) {
            const int dy = idx / HEX_K;
            const int dx = idx - dy * HEX_K;
            int m = m0 + dy;
            int n = n0 + dx;
            m = (m < 0) ? -m : ((m >= HEX_H) ? (2 * HEX_H - 2 - m) : m);
            n = (n < 0) ? -n : ((n >= HEX_W) ? (2 * HEX_W - 2 - n) : n);
            const int off = m * HEX_W + n;
            #pragma unroll
            for (int g = 0; g < HEX_G; g++)
                s[g] += __ldg(&img0[off + g * PLANE]);
        }
    }
}

__device__ __forceinline__ void reduce_store(float s[HEX_G], int lane,
                                             float* __restrict__ out,
                                             int grp, int o)
{
    #pragma unroll
    for (int off = 16; off > 0; off >>= 1) {
        #pragma unroll
        for (int g = 0; g < HEX_G; g++)
            s[g] += __shfl_xor_sync(0xffffffffu, s[g], off);
    }
    if (lane == 0) {
        const float inv = 1.0f / 81.0f;
        float* op = out + (size_t)(grp * HEX_G) * HEX_NOMM + o;
        #pragma unroll
        for (int g = 0; g < HEX_G; g++)
            op[g * HEX_NOMM] = s[g] * inv;
    }
}

__global__ __launch_bounds__(256)
void hexeye_kernel(const float* __restrict__ stim,
                   const int*   __restrict__ receptor_x,
                   const int*   __restrict__ receptor_y,
                   float*       __restrict__ out)
{
    const int gwarp = (blockIdx.x * blockDim.x + threadIdx.x) >> 5;
    const int lane  = threadIdx.x & 31;
    if (gwarp >= HEX_NWARP) return;

    const int pair = gwarp % HEX_NPAIR;      // receptor-minor
    const int grp  = gwarp / HEX_NPAIR;      // plane group (0..23)
    const int o0   = 2 * pair;
    const int o1   = o0 + 1;
    const bool hasB = (o1 < HEX_NOMM);

    const int row = lane / 3;                // 0..10 (valid < 9)
    const int seg = lane - row * 3;          // 0..2
    const int e0  = 4 * seg;
    const bool active = (lane < 27);

    const float* __restrict__ img0 = stim + (size_t)(grp * HEX_G) * PLANE;

    int   mA, nA, bA;  float xA, yA, zA, wA;  bool iA;
    int   mB, nB, bB;  float xB, yB, zB, wB;  bool iB;
    make_patch(receptor_x, receptor_y, o0, e0, mA, nA, bA, xA, yA, zA, wA, iA);
    make_patch(receptor_x, receptor_y, hasB ? o1 : o0, e0,
               mB, nB, bB, xB, yB, zB, wB, iB);

    float sA[HEX_G], sB[HEX_G];
    #pragma unroll
    for (int g = 0; g < HEX_G; g++) { sA[g] = 0.0f; sB[g] = 0.0f; }

    float4 v[HEX_G];

    // stage 1: issue loads for A
    if (iA) {
        if (active) {
            const float* p = img0 + (mA + row) * HEX_W + bA + e0;
            #pragma unroll
            for (int g = 0; g < HEX_G; g++)
                v[g] = __ldg((const float4*)(p + g * PLANE));
        }
    } else {
        gather_scalar(img0, mA, nA, lane, sA);
    }

    // stage 2: consume A
    if (iA && active) {
        #pragma unroll
        for (int g = 0; g < HEX_G; g++) {
            float t = v[g].x * xA;
            t = fmaf(v[g].y, yA, t);
            t = fmaf(v[g].z, zA, t);
            t = fmaf(v[g].w, wA, t);
            sA[g] = t;
        }
    }

    // stage 3: issue loads for B (overlaps A's reduction)
    if (hasB) {
        if (iB) {
            if (active) {
                const float* p = img0 + (mB + row) * HEX_W + bB + e0;
                #pragma unroll
                for (int g = 0; g < HEX_G; g++)
                    v[g] = __ldg((const float4*)(p + g * PLANE));
            }
        } else {
            gather_scalar(img0, mB, nB, lane, sB);
        }
    }

    // stage 4: reduce + store A under B's load latency
    reduce_store(sA, lane, out, grp, o0);

    // stage 5: consume, reduce, store B
    if (hasB) {
        if (iB && active) {
            #pragma unroll
            for (int g = 0; g < HEX_G; g++) {
                float t = v[g].x * xB;
                t = fmaf(v[g].y, yB, t);
                t = fmaf(v[g].z, zB, t);
                t = fmaf(v[g].w, wB, t);
                sB[g] = t;
            }
        }
        reduce_store(sB, lane, out, grp, o1);
    }
}

extern "C" void kernel_launch(void* const* d_in, const int* in_sizes, int n_in,
                              void* d_out, int out_size)
{
    const float* stim = (const float*)d_in[0];
    const int*   rx   = (const int*)d_in[1];
    const int*   ry   = (const int*)d_in[2];
    float*       out  = (float*)d_out;

    const int warps_per_block = 256 / 32;  // 8
    const int nblocks = (HEX_NWARP + warps_per_block - 1) / warps_per_block; // 1083

    hexeye_kernel<<<nblocks, 256>>>(stim, rx, ry, out);
}

// round 12
// speedup vs baseline: 1.1895x; 1.1895x over previous
#include <cuda_runtime.h>

// HexEye: mean over 9x9 reflect-padded patches at 721 receptor centers,
// for 32 batches x 3 channels of a 600x800 fp32 image.
//
// d_in[0]: stim        float32 [32, 3, 600, 800]
// d_in[1]: receptor_x  int32   [721]
// d_in[2]: receptor_y  int32   [721]
// d_out  : float32 [32, 3, 721]
//
// One warp per (receptor, group-of-8 bc planes).
// Fast path: lane -> (row = lane/3, seg = lane%3); each lane loads one
// aligned float4 => one LDG.128 with 27 active lanes fetches an entire 9x9
// patch per plane; 8 independent plane loads front-batched.
// Reduction: 3 butterfly stages on all 8 accumulators (xor 16/8/4), then
// each 4-lane group g selects accumulator g and finishes with xor 1/2;
// 8 stores distributed across lanes 0,4,...,28 (26 shuffles vs 40 naive,
// parallel stores instead of 8 serialized on lane 0).
// Slow path (border): exact jnp-'reflect' scalar gather.

#define HEX_H     600
#define HEX_W     800
#define HEX_K     9
#define HEX_PAD   4
#define HEX_NOMM  721
#define HEX_BC    96
#define HEX_G     8                         // bc planes per warp
#define HEX_NGRP  (HEX_BC / HEX_G)          // 12
#define HEX_NWARP (HEX_NGRP * HEX_NOMM)     // 8652
#define PLANE     (HEX_H * HEX_W)

__global__ __launch_bounds__(256)
void hexeye_kernel(const float* __restrict__ stim,
                   const int*   __restrict__ receptor_x,
                   const int*   __restrict__ receptor_y,
                   float*       __restrict__ out)
{
    const int gwarp = (blockIdx.x * blockDim.x + threadIdx.x) >> 5;
    const int lane  = threadIdx.x & 31;
    if (gwarp >= HEX_NWARP) return;

    const int o   = gwarp % HEX_NOMM;   // receptor id (receptor-minor)
    const int grp = gwarp / HEX_NOMM;   // plane group (0..11)

    int cx = __ldg(&receptor_x[o]);
    int cy = __ldg(&receptor_y[o]);
    cx = min(max(cx, HEX_PAD), HEX_W + HEX_PAD - 1);
    cy = min(max(cy, HEX_PAD), HEX_H + HEX_PAD - 1);

    const float* __restrict__ img0 = stim + (size_t)(grp * HEX_G) * PLANE;

    const int m0 = cy - 2 * HEX_PAD;        // top row     of patch
    const int n0 = cx - 2 * HEX_PAD;        // left column of patch
    const int base = n0 & ~3;               // 16B-aligned frame start
    const int w0   = n0 & 3;                // patch offset within frame

    float s[HEX_G];
    #pragma unroll
    for (int g = 0; g < HEX_G; g++) s[g] = 0.0f;

    const bool interior = (m0 >= 0) & (m0 + HEX_K <= HEX_H) &
                          (base >= 0) & (base + 12 <= HEX_W);

    if (interior) {
        // ---- fast vector path ----
        const int row = lane / 3;           // 0..10 (valid < 9)
        const int seg = lane - row * 3;     // 0..2
        const int e0  = 4 * seg;            // element index of v.x in frame

        // per-component weight: 1.0 iff w0 <= e < w0+9
        const float wx = ((e0 + 0 >= w0) & (e0 + 0 < w0 + HEX_K)) ? 1.0f : 0.0f;
        const float wy = ((e0 + 1 >= w0) & (e0 + 1 < w0 + HEX_K)) ? 1.0f : 0.0f;
        const float wz = ((e0 + 2 >= w0) & (e0 + 2 < w0 + HEX_K)) ? 1.0f : 0.0f;
        const float ww = ((e0 + 3 >= w0) & (e0 + 3 < w0 + HEX_K)) ? 1.0f : 0.0f;

        if (lane < 27) {
            const float* p0 = img0 + (m0 + row) * HEX_W + base + e0;
            float4 v[HEX_G];
            // front-batch all 8 independent 128-bit streaming loads
            #pragma unroll
            for (int g = 0; g < HEX_G; g++)
                v[g] = __ldcs((const float4*)(p0 + g * PLANE));
            #pragma unroll
            for (int g = 0; g < HEX_G; g++) {
                float t = v[g].x * wx;
                t = fmaf(v[g].y, wy, t);
                t = fmaf(v[g].z, wz, t);
                t = fmaf(v[g].w, ww, t);
                s[g] = t;
            }
        }
    } else {
        // ---- exact reflect scalar path (border receptors) ----
        #pragma unroll
        for (int i = 0; i < 3; i++) {
            const int idx = lane + 32 * i;          // 0..95, valid < 81
            if (idx < HEX_K * HEX_K) {
                const int dy = idx / HEX_K;
                const int dx = idx - dy * HEX_K;
                int m = m0 + dy;
                int n = n0 + dx;
                m = (m < 0) ? -m : ((m >= HEX_H) ? (2 * HEX_H - 2 - m) : m);
                n = (n < 0) ? -n : ((n >= HEX_W) ? (2 * HEX_W - 2 - n) : n);
                const int off = m * HEX_W + n;
                #pragma unroll
                for (int g = 0; g < HEX_G; g++)
                    s[g] += __ldg(&img0[off + g * PLANE]);
            }
        }
    }

    // ---- reduction ----
    // stage 1-3: butterfly over xor 16/8/4; afterwards lane l holds, for
    // every g, the partial sum over the 8 lanes sharing (l & 3).
    #pragma unroll
    for (int off = 16; off >= 4; off >>= 1) {
        #pragma unroll
        for (int g = 0; g < HEX_G; g++)
            s[g] += __shfl_xor_sync(0xffffffffu, s[g], off);
    }

    // stage 4: lane group g = lane>>2 selects accumulator g (static tree).
    const int sel = lane >> 2;              // 0..7
    float r = s[0];
    r = (sel == 1) ? s[1] : r;
    r = (sel == 2) ? s[2] : r;
    r = (sel == 3) ? s[3] : r;
    r = (sel == 4) ? s[4] : r;
    r = (sel == 5) ? s[5] : r;
    r = (sel == 6) ? s[6] : r;
    r = (sel == 7) ? s[7] : r;

    // stage 5: sum the 4 class partials within each 4-lane group.
    r += __shfl_xor_sync(0xffffffffu, r, 1);
    r += __shfl_xor_sync(0xffffffffu, r, 2);

    // lane 4g writes output for accumulator g (8 parallel stores).
    if ((lane & 3) == 0) {
        float* op = out + (size_t)(grp * HEX_G) * HEX_NOMM + o;
        op[sel * HEX_NOMM] = r * (1.0f / 81.0f);
    }
}

extern "C" void kernel_launch(void* const* d_in, const int* in_sizes, int n_in,
                              void* d_out, int out_size)
{
    const float* stim = (const float*)d_in[0];
    const int*   rx   = (const int*)d_in[1];
    const int*   ry   = (const int*)d_in[2];
    float*       out  = (float*)d_out;

    const int warps_per_block = 256 / 32;  // 8
    const int nblocks = (HEX_NWARP + warps_per_block - 1) / warps_per_block; // 1082

    hexeye_kernel<<<nblocks, 256>>>(stim, rx, ry, out);
}

// round 13
// speedup vs baseline: 1.2179x; 1.0239x over previous
#include <cuda_runtime.h>

// HexEye: mean over 9x9 reflect-padded patches at 721 receptor centers,
// for 32 batches x 3 channels of a 600x800 fp32 image.
//
// d_in[0]: stim        float32 [32, 3, 600, 800]
// d_in[1]: receptor_x  int32   [721]
// d_in[2]: receptor_y  int32   [721]
// d_out  : float32 [32, 3, 721]
//
// FINAL (converged): one warp per (receptor, group-of-8 bc planes).
// Fast path (patch fully interior): lane -> (row = lane/3, seg = lane%3);
// each lane loads one 16B-aligned float4, so ONE LDG.128 with 27 active
// lanes fetches an entire 9x9 patch for a plane. The 8 plane loads are
// independent and front-batched (__ldcs streaming: zero reuse).
// Slow path (patch touches border): exact jnp-'reflect' scalar gather.
//
// Why this is the floor: unique DRAM traffic (57.5 MB measured) equals the
// 64B-granule lower bound for scattered 36B patch rows; no pipe exceeds
// ~51%; 12 structural variants all land within [10.7, 13.1] us.

#define HEX_H     600
#define HEX_W     800
#define HEX_K     9
#define HEX_PAD   4
#define HEX_NOMM  721
#define HEX_BC    96
#define HEX_G     8                         // bc planes per warp
#define HEX_NGRP  (HEX_BC / HEX_G)          // 12
#define HEX_NWARP (HEX_NGRP * HEX_NOMM)     // 8652
#define PLANE     (HEX_H * HEX_W)

__global__ __launch_bounds__(256)
void hexeye_kernel(const float* __restrict__ stim,
                   const int*   __restrict__ receptor_x,
                   const int*   __restrict__ receptor_y,
                   float*       __restrict__ out)
{
    const int gwarp = (blockIdx.x * blockDim.x + threadIdx.x) >> 5;
    const int lane  = threadIdx.x & 31;
    if (gwarp >= HEX_NWARP) return;

    const int o   = gwarp % HEX_NOMM;   // receptor id (receptor-minor)
    const int grp = gwarp / HEX_NOMM;   // plane group (0..11)

    int cx = __ldg(&receptor_x[o]);
    int cy = __ldg(&receptor_y[o]);
    cx = min(max(cx, HEX_PAD), HEX_W + HEX_PAD - 1);
    cy = min(max(cy, HEX_PAD), HEX_H + HEX_PAD - 1);

    const float* __restrict__ img0 = stim + (size_t)(grp * HEX_G) * PLANE;

    const int m0 = cy - 2 * HEX_PAD;        // top row     of patch
    const int n0 = cx - 2 * HEX_PAD;        // left column of patch
    const int base = n0 & ~3;               // 16B-aligned frame start
    const int w0   = n0 & 3;                // patch offset within frame

    float s[HEX_G];
    #pragma unroll
    for (int g = 0; g < HEX_G; g++) s[g] = 0.0f;

    const bool interior = (m0 >= 0) & (m0 + HEX_K <= HEX_H) &
                          (base >= 0) & (base + 12 <= HEX_W);

    if (interior) {
        // ---- fast vector path ----
        const int row = lane / 3;           // 0..10 (valid < 9)
        const int seg = lane - row * 3;     // 0..2
        const int e0  = 4 * seg;            // element index of v.x in frame

        // per-component weight: 1.0 iff w0 <= e < w0+9
        const float wx = ((e0 + 0 >= w0) & (e0 + 0 < w0 + HEX_K)) ? 1.0f : 0.0f;
        const float wy = ((e0 + 1 >= w0) & (e0 + 1 < w0 + HEX_K)) ? 1.0f : 0.0f;
        const float wz = ((e0 + 2 >= w0) & (e0 + 2 < w0 + HEX_K)) ? 1.0f : 0.0f;
        const float ww = ((e0 + 3 >= w0) & (e0 + 3 < w0 + HEX_K)) ? 1.0f : 0.0f;

        if (lane < 27) {
            const float* p0 = img0 + (m0 + row) * HEX_W + base + e0;
            float4 v[HEX_G];
            // front-batch all 8 independent 128-bit streaming loads
            #pragma unroll
            for (int g = 0; g < HEX_G; g++)
                v[g] = __ldcs((const float4*)(p0 + g * PLANE));
            #pragma unroll
            for (int g = 0; g < HEX_G; g++) {
                float t = v[g].x * wx;
                t = fmaf(v[g].y, wy, t);
                t = fmaf(v[g].z, wz, t);
                t = fmaf(v[g].w, ww, t);
                s[g] = t;
            }
        }
    } else {
        // ---- exact reflect scalar path (border receptors) ----
        #pragma unroll
        for (int i = 0; i < 3; i++) {
            const int idx = lane + 32 * i;          // 0..95, valid < 81
            if (idx < HEX_K * HEX_K) {
                const int dy = idx / HEX_K;
                const int dx = idx - dy * HEX_K;
                int m = m0 + dy;
                int n = n0 + dx;
                m = (m < 0) ? -m : ((m >= HEX_H) ? (2 * HEX_H - 2 - m) : m);
                n = (n < 0) ? -n : ((n >= HEX_W) ? (2 * HEX_W - 2 - n) : n);
                const int off = m * HEX_W + n;
                #pragma unroll
                for (int g = 0; g < HEX_G; g++)
                    s[g] += __ldg(&img0[off + g * PLANE]);
            }
        }
    }

    // warp tree reductions
    #pragma unroll
    for (int off = 16; off > 0; off >>= 1) {
        #pragma unroll
        for (int g = 0; g < HEX_G; g++)
            s[g] += __shfl_xor_sync(0xffffffffu, s[g], off);
    }

    if (lane == 0) {
        const float inv = 1.0f / 81.0f;
        float* op = out + (size_t)(grp * HEX_G) * HEX_NOMM + o;
        #pragma unroll
        for (int g = 0; g < HEX_G; g++)
            op[g * HEX_NOMM] = s[g] * inv;
    }
}

extern "C" void kernel_launch(void* const* d_in, const int* in_sizes, int n_in,
                              void* d_out, int out_size)
{
    const float* stim = (const float*)d_in[0];
    const int*   rx   = (const int*)d_in[1];
    const int*   ry   = (const int*)d_in[2];
    float*       out  = (float*)d_out;

    const int warps_per_block = 256 / 32;  // 8
    const int nblocks = (HEX_NWARP + warps_per_block - 1) / warps_per_block; // 1082

    hexeye_kernel<<<nblocks, 256>>>(stim, rx, ry, out);
}